// round 17
// baseline (speedup 1.0000x reference)
#include <cuda_runtime.h>
#include <cuda_fp16.h>
#include <cstdint>
#include <math.h>

#define NB      4
#define DIMC    256
#define NSEQ    2048
#define HEADS   8
#define DHEAD   64
#define HIDDEN  512
#define QKV_CH  (3 * HIDDEN)
#define SCALE   0.125f
#define LOG2E   1.4426950408889634f

// ---------------- frag-major / paired fp16 storage ----------------
__device__ uint32_t g_wqf_hi[96 * 16 * 32 * 4], g_wqf_lo[96 * 16 * 32 * 4];
__device__ uint32_t g_wof_hi[16 * 32 * 32 * 4];
__device__ uint32_t g_xf_hi[NB * 16 * 256 * 32 * 2];
__device__ uint32_t g_qp_hi[NB * (HIDDEN/2) * NSEQ];
// K/V in B-frag-major order: [bh][t(32)][kt(4)][nt(8)][lane(32)] x uint2
__device__ uint32_t g_kf[NB * HEADS * 32 * 4 * 8 * 64];
__device__ uint32_t g_vf[NB * HEADS * 32 * 4 * 8 * 64];
__device__ uint32_t g_aop[NB * (HIDDEN/2) * NSEQ];

// ---------------- helpers ----------------
__device__ __forceinline__ void mma16816(float* c, const uint32_t* a,
                                         const uint32_t* b) {
    asm volatile(
        "mma.sync.aligned.m16n8k16.row.col.f32.f16.f16.f32 "
        "{%0,%1,%2,%3}, {%4,%5,%6,%7}, {%8,%9}, {%0,%1,%2,%3};"
        : "+f"(c[0]), "+f"(c[1]), "+f"(c[2]), "+f"(c[3])
        : "r"(a[0]), "r"(a[1]), "r"(a[2]), "r"(a[3]), "r"(b[0]), "r"(b[1]));
}
__device__ __forceinline__ uint32_t packh(float a, float b) {
    __half2 h = __floats2half2_rn(a, b);
    return *reinterpret_cast<uint32_t*>(&h);
}
__device__ __forceinline__ void splith(float f0, float f1,
                                       uint32_t& hi, uint32_t& lo) {
    __half h0 = __float2half_rn(f0), h1 = __float2half_rn(f1);
    hi = packh(f0, f1);
    lo = packh(f0 - __half2float(h0), f1 - __half2float(h1));
}
// pack two fp32 into half2 then exp2 both halves on MUFU
__device__ __forceinline__ uint32_t ex2_pair(float lo, float hi) {
    uint32_t w, p;
    asm("cvt.rn.f16x2.f32 %0, %1, %2;" : "=r"(w) : "f"(hi), "f"(lo));
    asm("ex2.approx.f16x2 %0, %1;" : "=r"(p) : "r"(w));
    return p;
}
__device__ __forceinline__ int bfrag(int kt, int nt, int lane) {
    return ((kt * 8 + nt) * 32 + lane) * 2;
}
__device__ __forceinline__ void cp16(uint32_t dst, const void* src) {
    asm volatile("cp.async.cg.shared.global [%0], [%1], 16;"
                 :: "r"(dst), "l"(src));
}
#define CP_COMMIT() asm volatile("cp.async.commit_group;" ::: "memory")
#define CP_WAIT(n)  asm volatile("cp.async.wait_group %0;" :: "n"(n) : "memory")

// ---------------- prep kernels (unchanged) ----------------
__global__ void pack_wq_frags(const float* __restrict__ w) {
    int tid = blockIdx.x * 256 + threadIdx.x;
    int lane = tid & 31, kt = (tid >> 5) & 15, mt = tid >> 9;
    int g = lane >> 2, qq = lane & 3;
    int r = mt * 16 + g, kc = kt * 16 + 2 * qq;
    uint4 hi, lo;
    splith(w[(size_t)r * DIMC + kc],           w[(size_t)r * DIMC + kc + 1],       hi.x, lo.x);
    splith(w[(size_t)(r + 8) * DIMC + kc],     w[(size_t)(r + 8) * DIMC + kc + 1], hi.y, lo.y);
    splith(w[(size_t)r * DIMC + kc + 8],       w[(size_t)r * DIMC + kc + 9],       hi.z, lo.z);
    splith(w[(size_t)(r + 8) * DIMC + kc + 8], w[(size_t)(r + 8) * DIMC + kc + 9], hi.w, lo.w);
    *reinterpret_cast<uint4*>(&g_wqf_hi[(size_t)tid * 4]) = hi;
    *reinterpret_cast<uint4*>(&g_wqf_lo[(size_t)tid * 4]) = lo;
}
__global__ void pack_wo_frags(const float* __restrict__ w) {
    int tid = blockIdx.x * 256 + threadIdx.x;
    int lane = tid & 31, kt = (tid >> 5) & 31, mt = tid >> 10;
    int g = lane >> 2, qq = lane & 3;
    int r = mt * 16 + g, kc = kt * 16 + 2 * qq;
    uint4 hi;
    hi.x = packh(w[(size_t)r * HIDDEN + kc],           w[(size_t)r * HIDDEN + kc + 1]);
    hi.y = packh(w[(size_t)(r + 8) * HIDDEN + kc],     w[(size_t)(r + 8) * HIDDEN + kc + 1]);
    hi.z = packh(w[(size_t)r * HIDDEN + kc + 8],       w[(size_t)r * HIDDEN + kc + 9]);
    hi.w = packh(w[(size_t)(r + 8) * HIDDEN + kc + 8], w[(size_t)(r + 8) * HIDDEN + kc + 9]);
    *reinterpret_cast<uint4*>(&g_wof_hi[(size_t)tid * 4]) = hi;
}
__global__ void pack_x_frags(const float* __restrict__ x) {
    int tid = blockIdx.x * 256 + threadIdx.x;
    int lane = tid & 31, ntg = (tid >> 5) & 255, kt = (tid >> 13) & 15, b = tid >> 17;
    int g = lane >> 2, qq = lane & 3;
    int n = ntg * 8 + g, k = kt * 16 + 2 * qq;
    uint2 hi;
    hi.x = packh(x[((size_t)b * DIMC + k) * NSEQ + n],
                 x[((size_t)b * DIMC + k + 1) * NSEQ + n]);
    hi.y = packh(x[((size_t)b * DIMC + k + 8) * NSEQ + n],
                 x[((size_t)b * DIMC + k + 9) * NSEQ + n]);
    *reinterpret_cast<uint2*>(&g_xf_hi[(size_t)tid * 2]) = hi;
}

// ============================================================================
// GEMM1: qkv = w_qkv @ x. 2-mma (w split, x hi). 128-thread CTAs, warps in a
// 2x2 grid, each warp 64m x 64n (47 B/mma -> tensor-bound, was 96 B/mma).
// Epilogue: Q -> paired fp16 hi, K -> g_kf, V -> g_vf frag-major.
// ============================================================================
__global__ __launch_bounds__(128, 2)
void gemm_qkv(void) {
    const int tid = threadIdx.x, wid = tid >> 5, lane = tid & 31;
    const int g = lane >> 2, qq = lane & 3;
    const int wm = wid >> 1, wn = wid & 1;
    const int m0 = blockIdx.y * 128, n0 = blockIdx.x * 128, b = blockIdx.z;
    const int mt0 = blockIdx.y * 8 + wm * 4;
    const int ntg0 = blockIdx.x * 16 + wn * 8;

    float acc[4][8][4] = {};

    for (int kt = 0; kt < 16; kt++) {
        uint4 ah[4], al[4];
#pragma unroll
        for (int mm = 0; mm < 4; mm++) {
            size_t ai = ((size_t)(mt0 + mm) * 16 + kt) * 128 + lane * 4;
            ah[mm] = *reinterpret_cast<const uint4*>(&g_wqf_hi[ai]);
            al[mm] = *reinterpret_cast<const uint4*>(&g_wqf_lo[ai]);
        }
#pragma unroll
        for (int nt = 0; nt < 8; nt++) {
            size_t bi = (((size_t)b * 16 + kt) * 256 + ntg0 + nt) * 64 + lane * 2;
            uint2 bh = *reinterpret_cast<const uint2*>(&g_xf_hi[bi]);
#pragma unroll
            for (int mm = 0; mm < 4; mm++) {
                mma16816(acc[mm][nt], (uint32_t*)&ah[mm], (uint32_t*)&bh);
                mma16816(acc[mm][nt], (uint32_t*)&al[mm], (uint32_t*)&bh);
            }
        }
    }

    const int by = blockIdx.y;
    const float QS = SCALE * LOG2E;
#pragma unroll
    for (int mm = 0; mm < 4; mm++) {
        int r0 = m0 + (wm * 4 + mm) * 16 + g;
#pragma unroll
        for (int nt = 0; nt < 8; nt++) {
            int c = n0 + (wn * 8 + nt) * 8 + 2 * qq;
            float v0 = acc[mm][nt][0], v1 = acc[mm][nt][1];
            float v2 = acc[mm][nt][2], v3 = acc[mm][nt][3];
            if (by < 8) {   // Q or K: pair channels via shfl
                if (by < 4) { v0 *= QS; v1 *= QS; v2 *= QS; v3 *= QS; }
                float p0 = __shfl_down_sync(0xffffffffu, v0, 4);
                float p1 = __shfl_down_sync(0xffffffffu, v1, 4);
                float p2 = __shfl_down_sync(0xffffffffu, v2, 4);
                float p3 = __shfl_down_sync(0xffffffffu, v3, 4);
                if (!(lane & 4)) {
                    if (by < 4) {
                        int pr = (b * (HIDDEN / 2)) + (r0 >> 1);
                        g_qp_hi[(size_t)pr * NSEQ + c]           = packh(v0, p0);
                        g_qp_hi[(size_t)pr * NSEQ + c + 1]       = packh(v1, p1);
                        g_qp_hi[(size_t)(pr + 4) * NSEQ + c]     = packh(v2, p2);
                        g_qp_hi[(size_t)(pr + 4) * NSEQ + c + 1] = packh(v3, p3);
                    } else {
                        int rk = r0 - HIDDEN;
                        int h_ = rk >> 6, d = rk & 63;
                        int kt_ = d >> 4, qq_ = (d & 15) >> 1;
                        int t_ = c >> 6, nt_ = (c >> 3) & 7, g_ = c & 7;
                        size_t fi = ((((size_t)(b * 8 + h_) * 32 + t_) * 4 + kt_) * 8 + nt_) * 64;
                        *reinterpret_cast<uint2*>(&g_kf[fi + (g_ * 4 + qq_) * 2]) =
                            make_uint2(packh(v0, p0), packh(v2, p2));
                        *reinterpret_cast<uint2*>(&g_kf[fi + ((g_ + 1) * 4 + qq_) * 2]) =
                            make_uint2(packh(v1, p1), packh(v3, p3));
                    }
                }
            } else {        // V: frag-major words (keys paired along seq)
                int ch = r0 - 2 * HIDDEN;
                int h_ = ch >> 6, d = ch & 63;
                int g_ = d & 7;
                int nt_a = (d >> 3) & 7, nt_b = ((d + 8) >> 3) & 7;
                int t_ = c >> 6, kt_ = (c >> 4) & 3, w = (c >> 3) & 1;
                size_t fi = ((((size_t)(b * 8 + h_) * 32 + t_) * 4 + kt_) * 8) * 64;
                int ln2 = (g_ * 4 + qq) * 2 + w;
                g_vf[fi + nt_a * 64 + ln2] = packh(v0, v1);
                g_vf[fi + nt_b * 64 + ln2] = packh(v2, v3);
            }
        }
    }
}

// ============================================================================
// Attention: M=32/warp, 128-thread CTAs, 2 CTA/SM, 3-stage cp.async smem ring.
// S loop fused nt-outer with inline fp16x2 exp so MUFU overlaps tensor.
// Row sums via ones-mma.
// ============================================================================
#define NT (NSEQ / 64)

__global__ __launch_bounds__(128, 2)
void attn_mma(void) {
    __shared__ uint32_t sK[3][2048], sV[3][2048];   // 48 KB
    const int tid = threadIdx.x, wid = tid >> 5, lane = tid & 31;
    const int g = lane >> 2, qq = lane & 3;
    const int bh = blockIdx.y, b = bh >> 3, h = bh & 7;
    const int q0 = blockIdx.x * 128;

    const size_t qBase = (size_t)(b * (HIDDEN / 2) + h * 32) * NSEQ;
    const uint32_t* __restrict__ kf = g_kf + (size_t)bh * (32 * 2048);
    const uint32_t* __restrict__ vf = g_vf + (size_t)bh * (32 * 2048);

    const uint32_t sKb = (uint32_t)__cvta_generic_to_shared(&sK[0][0]);
    const uint32_t sVb = (uint32_t)__cvta_generic_to_shared(&sV[0][0]);

    // ---- hoist Q frags (hi only) for both 16-row subtiles ----
    uint32_t ah[2][4][4];
#pragma unroll
    for (int m = 0; m < 2; m++) {
        const int qrow = q0 + wid * 32 + m * 16 + g;
#pragma unroll
        for (int kt = 0; kt < 4; kt++) {
            size_t pq = qBase + (size_t)(kt * 8 + qq) * NSEQ;
            ah[m][kt][0] = g_qp_hi[pq + qrow];
            ah[m][kt][1] = g_qp_hi[pq + qrow + 8];
            ah[m][kt][2] = g_qp_hi[pq + 4 * NSEQ + qrow];
            ah[m][kt][3] = g_qp_hi[pq + 4 * NSEQ + qrow + 8];
        }
    }

    auto issue_tile = [&](int t) {
        const int st = t % 3;
        const uint32_t* ks = kf + t * 2048 + tid * 4;
        const uint32_t* vs = vf + t * 2048 + tid * 4;
        uint32_t dK = sKb + (st * 2048 + tid * 4) * 4;
        uint32_t dV = sVb + (st * 2048 + tid * 4) * 4;
#pragma unroll
        for (int c = 0; c < 4; c++) {
            cp16(dK + c * 2048, ks + c * 512);
            cp16(dV + c * 2048, vs + c * 512);
        }
        CP_COMMIT();
    };

    issue_tile(0);
    issue_tile(1);

    float O[2][8][4] = {};
    float Lrow[2][4] = {};
    const uint32_t ones2[2] = {0x3C003C00u, 0x3C003C00u};

    for (int t = 0; t < NT; t++) {
        if (t + 1 < NT) { CP_WAIT(1); } else { CP_WAIT(0); }
        __syncthreads();
        if (t + 2 < NT) issue_tile(t + 2);

        const int st = t % 3;
        const uint32_t* sk = &sK[st][lane * 2];
        const uint32_t* sv = &sV[st][lane * 2];

        // ---- fused S + exp: per nt, 4 LDS + 8 mma + 2x2 ex2_pair ----
        uint32_t Phi[2][4][4];
#pragma unroll
        for (int nt = 0; nt < 8; nt++) {
            uint2 b2[4];
#pragma unroll
            for (int kt = 0; kt < 4; kt++)
                b2[kt] = *reinterpret_cast<const uint2*>(&sk[(kt * 8 + nt) * 64]);
            float acc[2][4] = {};
#pragma unroll
            for (int kt = 0; kt < 4; kt++)
#pragma unroll
                for (int m = 0; m < 2; m++)
                    mma16816(acc[m], ah[m][kt], (uint32_t*)&b2[kt]);
            int kt2 = nt >> 1, base = (nt & 1) * 2;
#pragma unroll
            for (int m = 0; m < 2; m++) {
                Phi[m][kt2][base]     = ex2_pair(acc[m][0], acc[m][1]);
                Phi[m][kt2][base + 1] = ex2_pair(acc[m][2], acc[m][3]);
            }
        }

        // ---- row sums via ones-mma ----
#pragma unroll
        for (int m = 0; m < 2; m++)
#pragma unroll
            for (int kt2 = 0; kt2 < 4; kt2++)
                mma16816(Lrow[m], Phi[m][kt2], ones2);

        // ---- O += P V ----
#pragma unroll
        for (int ktp = 0; ktp < 4; ktp++) {
            uint2 v2[8];
#pragma unroll
            for (int nt = 0; nt < 8; nt++)
                v2[nt] = *reinterpret_cast<const uint2*>(&sv[(ktp * 8 + nt) * 64]);
#pragma unroll
            for (int nt = 0; nt < 8; nt++)
#pragma unroll
                for (int m = 0; m < 2; m++)
                    mma16816(O[m][nt], Phi[m][ktp], (uint32_t*)&v2[nt]);
        }
    }

    // ---- epilogue ----
    const size_t aBase = (size_t)(b * (HIDDEN / 2) + h * 32) * NSEQ;
#pragma unroll
    for (int m = 0; m < 2; m++) {
        const float ig = 1.0f / Lrow[m][0], ig8 = 1.0f / Lrow[m][2];
        const int qrow = q0 + wid * 32 + m * 16 + g;
#pragma unroll
        for (int nt = 0; nt < 8; nt++) {
            size_t pr = aBase + (size_t)(nt * 4 + qq) * NSEQ;
            g_aop[pr + qrow]     = packh(O[m][nt][0] * ig,  O[m][nt][1] * ig);
            g_aop[pr + qrow + 8] = packh(O[m][nt][2] * ig8, O[m][nt][3] * ig8);
        }
    }
}

// ============================================================================
// GEMM3 (unchanged): 1-mma (w hi, ao hi).
// ============================================================================
__global__ __launch_bounds__(256, 2)
void gemm_out(const float* __restrict__ bias, float* __restrict__ out) {
    __shared__ uint32_t sBH[2048];
    const int tid = threadIdx.x, wid = tid >> 5, lane = tid & 31;
    const int g = lane >> 2, qq = lane & 3;
    const int wm = wid >> 1, wn = wid & 1;
    const int m0 = blockIdx.y * 128, n0 = blockIdx.x * 64, b = blockIdx.z;
    const int mt0 = blockIdx.y * 8 + 2 * wm;

    float acc[2][4][4] = {};

    for (int kc4 = 0; kc4 < 8; kc4++) {
#pragma unroll
        for (int i = 0; i < 4; i++) {
            int idx = wid * 4 + i, kt = idx >> 3, nt = idx & 7;
            int pr = b * (HIDDEN / 2) + kc4 * 32 + kt * 8 + qq;
            int col = n0 + nt * 8 + g;
            int o = bfrag(kt, nt, lane);
            sBH[o]     = g_aop[(size_t)pr * NSEQ + col];
            sBH[o + 1] = g_aop[(size_t)(pr + 4) * NSEQ + col];
        }
        __syncthreads();

#pragma unroll
        for (int kt = 0; kt < 4; kt++) {
            int ktg = kc4 * 4 + kt;
            uint4 ah[2];
#pragma unroll
            for (int mm = 0; mm < 2; mm++) {
                size_t ai = ((size_t)(mt0 + mm) * 32 + ktg) * 128 + lane * 4;
                ah[mm] = *reinterpret_cast<const uint4*>(&g_wof_hi[ai]);
            }
#pragma unroll
            for (int nt = 0; nt < 4; nt++) {
                uint2 bh = *reinterpret_cast<uint2*>(&sBH[bfrag(kt, wn * 4 + nt, lane)]);
#pragma unroll
                for (int mm = 0; mm < 2; mm++)
                    mma16816(acc[mm][nt], (uint32_t*)&ah[mm], (uint32_t*)&bh);
            }
        }
        __syncthreads();
    }

#pragma unroll
    for (int mm = 0; mm < 2; mm++) {
        int r0 = m0 + (2 * wm + mm) * 16 + g;
        float b0 = bias[r0], b8 = bias[r0 + 8];
        float* cp0 = out + (size_t)(b * DIMC + r0) * NSEQ;
        float* cp8 = out + (size_t)(b * DIMC + r0 + 8) * NSEQ;
#pragma unroll
        for (int nt = 0; nt < 4; nt++) {
            int c = n0 + (wn * 4 + nt) * 8 + 2 * qq;
            *reinterpret_cast<float2*>(cp0 + c) =
                make_float2(acc[mm][nt][0] + b0, acc[mm][nt][1] + b0);
            *reinterpret_cast<float2*>(cp8 + c) =
                make_float2(acc[mm][nt][2] + b8, acc[mm][nt][3] + b8);
        }
    }
}

// ============================================================================
extern "C" void kernel_launch(void* const* d_in, const int* in_sizes, int n_in,
                              void* d_out, int out_size) {
    const float* x     = (const float*)d_in[0];
    const float* w_qkv = (const float*)d_in[1];
    const float* w_out = (const float*)d_in[2];
    const float* b_out = (const float*)d_in[3];
    float* out = (float*)d_out;

    pack_wq_frags<<<192, 256>>>(w_qkv);
    pack_wo_frags<<<64, 256>>>(w_out);
    pack_x_frags<<<2048, 256>>>(x);

    dim3 g1(NSEQ / 128, QKV_CH / 128, NB);
    gemm_qkv<<<g1, 128>>>();

    dim3 g2(NSEQ / 128, NB * HEADS);
    attn_mma<<<g2, 128>>>();

    dim3 g3(NSEQ / 64, DIMC / 128, NB);
    gemm_out<<<g3, 256>>>(b_out, out);
}